// round 16
// baseline (speedup 1.0000x reference)
#include <cuda_runtime.h>
#include <cuda_bf16.h>
#include <cstdint>
#include <cstddef>

#define H_    300000
#define CIN   16
#define COUT  32
#define KK    27
#define HB    128
#define TB    128
#define NBLK  ((H_ + HB - 1) / HB)    // 2344
#define NPART (NBLK * 4)              // one partial per (o, block, warp)
#define NIDX  (H_ * KK)
#define ROWB  80                      // A row stride: hi(32B) | lo(32B) | pad(16B)
#define STAGEB (HB * ROWB)            // 10240 B per stage
#define NSTAGE 3
#define SCHUNK 8                      // stats reduction chunks per row
#define PREPB  ((H_ + 255) / 256)     // 1172 split_x blocks in merged prep
#define OPITCH 33                     // epilogue staging pitch (floats)

// Scratch (static device globals: allocation-free per harness rules)
__device__ uint4  g_xbf[(size_t)H_ * 4];       // per h: 64B = 16 hi bf16 | 16 lo bf16
__device__ uint2  g_bfrag[KK * 2 * 4 * 32];    // mma B fragments [(k*2+s)*4+nt][lane]
__device__ float  g_partials[64 * NPART];
__device__ double g_red[64 * SCHUNK];          // stats stage-1 output
__device__ int    g_is64;

#define MMA_BF16(D, A, B)                                                     \
    asm volatile("mma.sync.aligned.m16n8k16.row.col.f32.bf16.bf16.f32 "       \
                 "{%0,%1,%2,%3}, {%4,%5,%6,%7}, {%8,%9}, {%0,%1,%2,%3};"      \
                 : "+f"((D)[0]), "+f"((D)[1]), "+f"((D)[2]), "+f"((D)[3])     \
                 : "r"((A)[0]), "r"((A)[1]), "r"((A)[2]), "r"((A)[3]),        \
                   "r"((B).x), "r"((B).y))

// ---------------------------------------------------------------------------
// Kernel 1 (merged prep): blocks [0, PREPB) = split_x; PREPB..PREPB+13 = wfrag;
// last block = detect.
// ---------------------------------------------------------------------------
__global__ void prep_kernel(const float* __restrict__ x,
                            const float* __restrict__ w,
                            const unsigned int* __restrict__ nv) {
    const int b = blockIdx.x;
    if (b < PREPB) {
        int h = b * 256 + threadIdx.x;
        if (h < H_) {
            unsigned int hw[8], lw[8];
#pragma unroll
            for (int t = 0; t < 8; t++) {
                float v0 = x[(size_t)(2 * t) * H_ + h];
                float v1 = x[(size_t)(2 * t + 1) * H_ + h];
                __nv_bfloat16 h0 = __float2bfloat16(v0), h1 = __float2bfloat16(v1);
                __nv_bfloat16 l0 = __float2bfloat16(v0 - __bfloat162float(h0));
                __nv_bfloat16 l1 = __float2bfloat16(v1 - __bfloat162float(h1));
                hw[t] = (unsigned)__bfloat16_as_ushort(h0) |
                        ((unsigned)__bfloat16_as_ushort(h1) << 16);
                lw[t] = (unsigned)__bfloat16_as_ushort(l0) |
                        ((unsigned)__bfloat16_as_ushort(l1) << 16);
            }
            g_xbf[(size_t)h * 4 + 0] = make_uint4(hw[0], hw[1], hw[2], hw[3]);
            g_xbf[(size_t)h * 4 + 1] = make_uint4(hw[4], hw[5], hw[6], hw[7]);
            g_xbf[(size_t)h * 4 + 2] = make_uint4(lw[0], lw[1], lw[2], lw[3]);
            g_xbf[(size_t)h * 4 + 3] = make_uint4(lw[4], lw[5], lw[6], lw[7]);
        }
    } else if (b < PREPB + 14) {
        int t = (b - PREPB) * 256 + threadIdx.x;
        if (t < KK * 4 * 32) {
            int lane = t & 31;
            int nt   = (t >> 5) & 3;
            int k    = t >> 7;
            int o    = nt * 8 + (lane >> 2);
            int i0   = 2 * (lane & 3);
            int ii[4] = {i0, i0 + 1, i0 + 8, i0 + 9};
            unsigned short hi[4], lo[4];
#pragma unroll
            for (int j = 0; j < 4; j++) {
                float vv = w[(o * CIN + ii[j]) * KK + k];
                __nv_bfloat16 bh = __float2bfloat16(vv);
                __nv_bfloat16 bl = __float2bfloat16(vv - __bfloat162float(bh));
                hi[j] = __bfloat16_as_ushort(bh);
                lo[j] = __bfloat16_as_ushort(bl);
            }
            uint2 Hf, Lf;
            Hf.x = (unsigned)hi[0] | ((unsigned)hi[1] << 16);
            Hf.y = (unsigned)hi[2] | ((unsigned)hi[3] << 16);
            Lf.x = (unsigned)lo[0] | ((unsigned)lo[1] << 16);
            Lf.y = (unsigned)lo[2] | ((unsigned)lo[3] << 16);
            g_bfrag[((k * 2 + 0) * 4 + nt) * 32 + lane] = Hf;
            g_bfrag[((k * 2 + 1) * 4 + nt) * 32 + lane] = Lf;
        }
    } else {
        __shared__ int ok;
        if (threadIdx.x == 0) ok = 1;
        __syncthreads();
        unsigned int v = nv[threadIdx.x * 8000 + 1];
        if (v != 0u && v != 0xFFFFFFFFu) ok = 0;
        __syncthreads();
        if (threadIdx.x == 0) g_is64 = ok;
    }
}

// ---------------------------------------------------------------------------
// Kernel 2: HMMA conv (warp-local cp.async pipeline, register-prefetched
// indices) + coalesced epilogue. CRITICAL: one __syncthreads() after the
// mainloop drains, BEFORE reusing Ab as the output staging buffer — warps run
// unsynchronized in the mainloop, so a fast warp must not clobber a slow
// warp's in-flight A tiles (the R15 race).
// ---------------------------------------------------------------------------
__global__ void __launch_bounds__(TB, 6) conv_kernel(const int* __restrict__ neigh32,
                                                     float* __restrict__ out) {
    __shared__ __align__(128) char Ab[NSTAGE * STAGEB];   // 30720 B

    const int tid  = threadIdx.x;
    const int lane = tid & 31;
    const int wid  = tid >> 5;
    const int h0   = blockIdx.x * HB;
    const int is64 = g_is64;
    const uint32_t sbase = (uint32_t)__cvta_generic_to_shared(Ab);

    const int q  = lane & 3;
    const int rl = lane >> 2;       // 0..7
    const int step = is64 ? 2 : 1;

    uint32_t dsto[4];
    int      gbase[4];
    bool     rvalid[4];
#pragma unroll
    for (int j = 0; j < 4; j++) {
        int r     = wid * 32 + rl + 8 * j;
        dsto[j]   = (uint32_t)(r * ROWB + q * 16);
        int h     = h0 + r;
        rvalid[j] = (h < H_);
        gbase[j]  = (rvalid[j] ? h : 0) * KK * step;
    }

    int pidx[4];
    auto loadidx = [&](int k) {
#pragma unroll
        for (int j = 0; j < 4; j++)
            pidx[j] = rvalid[j] ? neigh32[gbase[j] + k * step] : -1;
    };
    auto issue = [&](int k) {
        uint32_t dstb = sbase + (k % NSTAGE) * STAGEB;
#pragma unroll
        for (int j = 0; j < 4; j++) {
            unsigned ok = ((unsigned)pidx[j] < (unsigned)H_) ? 16u : 0u;
            const uint4* src = g_xbf + ((size_t)(ok ? pidx[j] : 0) * 4 + q);
            asm volatile("cp.async.cg.shared.global [%0], [%1], 16, %2;"
                         :: "r"(dstb + dsto[j]), "l"(src), "r"(ok) : "memory");
        }
        asm volatile("cp.async.commit_group;" ::: "memory");
    };

    const int rowl = (lane & 7) + ((lane >> 3) & 1) * 8;
    const int byof = (lane >> 4) * 16;

    float d[2][4][4];
#pragma unroll
    for (int a = 0; a < 2; a++)
#pragma unroll
        for (int b = 0; b < 4; b++)
#pragma unroll
            for (int c = 0; c < 4; c++) d[a][b][c] = 0.f;

    loadidx(0); issue(0);
    loadidx(1); issue(1);
    loadidx(2);

#pragma unroll 1
    for (int k = 0; k < KK; k++) {
        if (k + 2 < KK) {
            issue(k + 2);
            if (k + 3 < KK) loadidx(k + 3);
        } else {
            asm volatile("cp.async.commit_group;" ::: "memory");
        }
        asm volatile("cp.async.wait_group 2;" ::: "memory");
        __syncwarp();

        const uint32_t bufb = sbase + (k % NSTAGE) * STAGEB;
        uint32_t aH[2][4], aL[2][4];
#pragma unroll
        for (int mt = 0; mt < 2; mt++) {
            uint32_t ah = bufb + (wid * 32 + mt * 16 + rowl) * ROWB + byof;
            uint32_t al = ah + 32;
            asm volatile("ldmatrix.sync.aligned.m8n8.x4.shared.b16 {%0,%1,%2,%3}, [%4];"
                         : "=r"(aH[mt][0]), "=r"(aH[mt][1]), "=r"(aH[mt][2]), "=r"(aH[mt][3])
                         : "r"(ah));
            asm volatile("ldmatrix.sync.aligned.m8n8.x4.shared.b16 {%0,%1,%2,%3}, [%4];"
                         : "=r"(aL[mt][0]), "=r"(aL[mt][1]), "=r"(aL[mt][2]), "=r"(aL[mt][3])
                         : "r"(al));
        }
#pragma unroll
        for (int nt = 0; nt < 4; nt++) {
            uint2 bh = __ldg(&g_bfrag[((k * 2 + 0) * 4 + nt) * 32 + lane]);
            uint2 bl = __ldg(&g_bfrag[((k * 2 + 1) * 4 + nt) * 32 + lane]);
#pragma unroll
            for (int mt = 0; mt < 2; mt++) {
                MMA_BF16(d[mt][nt], aH[mt], bh);
                MMA_BF16(d[mt][nt], aH[mt], bl);
                MMA_BF16(d[mt][nt], aL[mt], bh);
            }
        }
        __syncwarp();
    }
    asm volatile("cp.async.wait_group 0;" ::: "memory");

    // BN partials from register fragments (deterministic, warp-private).
    const int pidx2 = blockIdx.x * 4 + wid;
#pragma unroll
    for (int nt = 0; nt < 4; nt++) {
        float s0 = 0.f, s1 = 0.f, q0 = 0.f, q1 = 0.f;
#pragma unroll
        for (int mt = 0; mt < 2; mt++) {
            float c0 = d[mt][nt][0], c1 = d[mt][nt][1];
            float c2 = d[mt][nt][2], c3 = d[mt][nt][3];
            s0 += c0 + c2; s1 += c1 + c3;
            q0 += c0 * c0 + c2 * c2; q1 += c1 * c1 + c3 * c3;
        }
#pragma unroll
        for (int off = 4; off < 32; off <<= 1) {
            s0 += __shfl_xor_sync(0xffffffffu, s0, off);
            s1 += __shfl_xor_sync(0xffffffffu, s1, off);
            q0 += __shfl_xor_sync(0xffffffffu, q0, off);
            q1 += __shfl_xor_sync(0xffffffffu, q1, off);
        }
        if ((lane >> 2) == 0) {
            int o0 = nt * 8 + 2 * lane;
            g_partials[o0 * NPART + pidx2]            = s0;
            g_partials[(o0 + 1) * NPART + pidx2]      = s1;
            g_partials[(32 + o0) * NPART + pidx2]     = q0;
            g_partials[(32 + o0 + 1) * NPART + pidx2] = q1;
        }
    }

    // ALL warps' mainloops and cp.async traffic must be complete before Ab is
    // repurposed — warps are otherwise unsynchronized (this was the R15 race).
    __syncthreads();

    // Coalesced epilogue: stage D in warp-private smem region, then float4 STG.
    {
        float* stg = reinterpret_cast<float*>(Ab) + wid * (COUT * OPITCH);
#pragma unroll
        for (int nt = 0; nt < 4; nt++) {
            int o0 = nt * 8 + 2 * (lane & 3);
#pragma unroll
            for (int mt = 0; mt < 2; mt++) {
                int hp = mt * 16 + (lane >> 2);     // 0..31 within warp
                stg[o0 * OPITCH + hp]           = d[mt][nt][0];
                stg[(o0 + 1) * OPITCH + hp]     = d[mt][nt][1];
                stg[o0 * OPITCH + hp + 8]       = d[mt][nt][2];
                stg[(o0 + 1) * OPITCH + hp + 8] = d[mt][nt][3];
            }
        }
        __syncwarp();
        const int hq = lane & 7;                    // float4 index along h
        const int h  = h0 + wid * 32 + 4 * hq;      // mult of 4; H_%4==0
        if (h < H_) {
#pragma unroll
            for (int g = 0; g < 8; g++) {
                int o = (lane >> 3) + 4 * g;
                const float* p = stg + o * OPITCH + 4 * hq;
                float4 v = make_float4(p[0], p[1], p[2], p[3]);
                *reinterpret_cast<float4*>(out + (size_t)o * H_ + h) = v;
            }
        }
    }
}

// ---------------------------------------------------------------------------
// Kernel 3: stats stage 1 — 64 rows x SCHUNK chunks; deterministic fp64 tree.
// ---------------------------------------------------------------------------
__global__ void stats1_kernel() {
    const int row   = blockIdx.x;
    const int chunk = blockIdx.y;
    const int per   = (NPART + SCHUNK - 1) / SCHUNK;
    const int b0    = chunk * per;
    const int b1    = (b0 + per < NPART) ? b0 + per : NPART;
    double s = 0.0;
    for (int b = b0 + threadIdx.x; b < b1; b += blockDim.x)
        s += (double)g_partials[row * NPART + b];
    __shared__ double r[256];
    r[threadIdx.x] = s;
    __syncthreads();
    for (int sft = 128; sft > 0; sft >>= 1) {
        if (threadIdx.x < sft) r[threadIdx.x] += r[threadIdx.x + sft];
        __syncthreads();
    }
    if (threadIdx.x == 0) g_red[row * SCHUNK + chunk] = r[0];
}

// ---------------------------------------------------------------------------
// Kernel 4: normalize in place; folds the per-channel chunk-sum reduction
// inline — 16 uniform loads, deterministic order.
// ---------------------------------------------------------------------------
__global__ void bn_kernel(const float* __restrict__ gamma,
                          const float* __restrict__ beta,
                          float* __restrict__ out) {
    const int o = blockIdx.y;
    double s1 = 0.0, s2 = 0.0;
#pragma unroll
    for (int c = 0; c < SCHUNK; c++) {
        s1 += g_red[o * SCHUNK + c];
        s2 += g_red[(32 + o) * SCHUNK + c];
    }
    double mean = s1 / (double)H_;
    double var  = s2 / (double)H_ - mean * mean;
    float rstd  = rsqrtf((float)(var + 1e-5));
    float sc    = rstd * gamma[o];
    float bi    = beta[o] - (float)mean * sc;

    const int t = blockIdx.x * blockDim.x + threadIdx.x;
    float4* p = reinterpret_cast<float4*>(out + (size_t)o * H_);
    if (t < H_ / 4) {
        float4 v = p[t];
        v.x = v.x * sc + bi;
        v.y = v.y * sc + bi;
        v.z = v.z * sc + bi;
        v.w = v.w * sc + bi;
        p[t] = v;
    }
}

// ---------------------------------------------------------------------------
extern "C" void kernel_launch(void* const* d_in, const int* in_sizes, int n_in,
                              void* d_out, int out_size) {
    const float* x     = (const float*)d_in[0];  // (1,16,300000,1)
    const float* w     = (const float*)d_in[1];  // (32,16,27)
    const float* gamma = (const float*)d_in[2];  // (32,)
    const float* beta  = (const float*)d_in[3];  // (32,)
    const void*  neigh = d_in[4];                // (300000,27) i64 or i32
    float*       out   = (float*)d_out;          // (1,32,300000,1)

    cudaFuncSetAttribute(conv_kernel,
                         cudaFuncAttributePreferredSharedMemoryCarveout,
                         cudaSharedmemCarveoutMaxShared);

    prep_kernel<<<PREPB + 15, 256>>>(x, w, (const unsigned int*)neigh);
    conv_kernel<<<NBLK, TB>>>((const int*)neigh, out);
    stats1_kernel<<<dim3(64, SCHUNK), 256>>>();
    bn_kernel<<<dim3((H_ / 4 + 255) / 256, COUT), 256>>>(gamma, beta, out);
}

// round 17
// speedup vs baseline: 2.0235x; 2.0235x over previous
#include <cuda_runtime.h>
#include <cuda_bf16.h>
#include <cstdint>
#include <cstddef>

#define H_    300000
#define CIN   16
#define COUT  32
#define KK    27
#define HB    128
#define TB    128
#define NBLK  ((H_ + HB - 1) / HB)    // 2344
#define NPART (NBLK * 4)              // one partial per (o, block, warp)
#define NIDX  (H_ * KK)
#define ROWB  80                      // A row stride: hi(32B) | lo(32B) | pad(16B)
#define STAGEB (HB * ROWB)            // 10240 B per stage
#define NSTAGE 3
#define SCHUNK 8                      // stats reduction chunks per row
#define PREPB  ((H_ + 255) / 256)     // 1172 split_x blocks in merged prep
#define OPITCH 33                     // epilogue staging pitch (floats)

// Scratch (static device globals: allocation-free per harness rules)
__device__ uint4  g_xbf[(size_t)H_ * 4];       // per h: 64B = 16 hi bf16 | 16 lo bf16
__device__ uint2  g_bfrag[KK * 2 * 4 * 32];    // mma B fragments [(k*2+s)*4+nt][lane]
__device__ float  g_partials[64 * NPART];
__device__ double g_red[64 * SCHUNK];          // stats stage-1 output
__device__ float  g_scale[COUT];
__device__ float  g_bias[COUT];
__device__ int    g_is64;

#define MMA_BF16(D, A, B)                                                     \
    asm volatile("mma.sync.aligned.m16n8k16.row.col.f32.bf16.bf16.f32 "       \
                 "{%0,%1,%2,%3}, {%4,%5,%6,%7}, {%8,%9}, {%0,%1,%2,%3};"      \
                 : "+f"((D)[0]), "+f"((D)[1]), "+f"((D)[2]), "+f"((D)[3])     \
                 : "r"((A)[0]), "r"((A)[1]), "r"((A)[2]), "r"((A)[3]),        \
                   "r"((B).x), "r"((B).y))

// ---------------------------------------------------------------------------
// Kernel 1 (merged prep): blocks [0, PREPB) = split_x; PREPB..PREPB+13 = wfrag;
// last block = detect.
// ---------------------------------------------------------------------------
__global__ void prep_kernel(const float* __restrict__ x,
                            const float* __restrict__ w,
                            const unsigned int* __restrict__ nv) {
    const int b = blockIdx.x;
    if (b < PREPB) {
        int h = b * 256 + threadIdx.x;
        if (h < H_) {
            unsigned int hw[8], lw[8];
#pragma unroll
            for (int t = 0; t < 8; t++) {
                float v0 = x[(size_t)(2 * t) * H_ + h];
                float v1 = x[(size_t)(2 * t + 1) * H_ + h];
                __nv_bfloat16 h0 = __float2bfloat16(v0), h1 = __float2bfloat16(v1);
                __nv_bfloat16 l0 = __float2bfloat16(v0 - __bfloat162float(h0));
                __nv_bfloat16 l1 = __float2bfloat16(v1 - __bfloat162float(h1));
                hw[t] = (unsigned)__bfloat16_as_ushort(h0) |
                        ((unsigned)__bfloat16_as_ushort(h1) << 16);
                lw[t] = (unsigned)__bfloat16_as_ushort(l0) |
                        ((unsigned)__bfloat16_as_ushort(l1) << 16);
            }
            g_xbf[(size_t)h * 4 + 0] = make_uint4(hw[0], hw[1], hw[2], hw[3]);
            g_xbf[(size_t)h * 4 + 1] = make_uint4(hw[4], hw[5], hw[6], hw[7]);
            g_xbf[(size_t)h * 4 + 2] = make_uint4(lw[0], lw[1], lw[2], lw[3]);
            g_xbf[(size_t)h * 4 + 3] = make_uint4(lw[4], lw[5], lw[6], lw[7]);
        }
    } else if (b < PREPB + 14) {
        int t = (b - PREPB) * 256 + threadIdx.x;
        if (t < KK * 4 * 32) {
            int lane = t & 31;
            int nt   = (t >> 5) & 3;
            int k    = t >> 7;
            int o    = nt * 8 + (lane >> 2);
            int i0   = 2 * (lane & 3);
            int ii[4] = {i0, i0 + 1, i0 + 8, i0 + 9};
            unsigned short hi[4], lo[4];
#pragma unroll
            for (int j = 0; j < 4; j++) {
                float vv = w[(o * CIN + ii[j]) * KK + k];
                __nv_bfloat16 bh = __float2bfloat16(vv);
                __nv_bfloat16 bl = __float2bfloat16(vv - __bfloat162float(bh));
                hi[j] = __bfloat16_as_ushort(bh);
                lo[j] = __bfloat16_as_ushort(bl);
            }
            uint2 Hf, Lf;
            Hf.x = (unsigned)hi[0] | ((unsigned)hi[1] << 16);
            Hf.y = (unsigned)hi[2] | ((unsigned)hi[3] << 16);
            Lf.x = (unsigned)lo[0] | ((unsigned)lo[1] << 16);
            Lf.y = (unsigned)lo[2] | ((unsigned)lo[3] << 16);
            g_bfrag[((k * 2 + 0) * 4 + nt) * 32 + lane] = Hf;
            g_bfrag[((k * 2 + 1) * 4 + nt) * 32 + lane] = Lf;
        }
    } else {
        __shared__ int ok;
        if (threadIdx.x == 0) ok = 1;
        __syncthreads();
        unsigned int v = nv[threadIdx.x * 8000 + 1];
        if (v != 0u && v != 0xFFFFFFFFu) ok = 0;
        __syncthreads();
        if (threadIdx.x == 0) g_is64 = ok;
    }
}

// ---------------------------------------------------------------------------
// Kernel 2: HMMA conv (warp-local cp.async pipeline, register-prefetched
// indices) + coalesced epilogue. One __syncthreads() after the mainloop
// drains, BEFORE reusing Ab as the output staging buffer (R15-race fix).
// ---------------------------------------------------------------------------
__global__ void __launch_bounds__(TB, 6) conv_kernel(const int* __restrict__ neigh32,
                                                     float* __restrict__ out) {
    __shared__ __align__(128) char Ab[NSTAGE * STAGEB];   // 30720 B

    const int tid  = threadIdx.x;
    const int lane = tid & 31;
    const int wid  = tid >> 5;
    const int h0   = blockIdx.x * HB;
    const int is64 = g_is64;
    const uint32_t sbase = (uint32_t)__cvta_generic_to_shared(Ab);

    const int q  = lane & 3;
    const int rl = lane >> 2;       // 0..7
    const int step = is64 ? 2 : 1;

    uint32_t dsto[4];
    int      gbase[4];
    bool     rvalid[4];
#pragma unroll
    for (int j = 0; j < 4; j++) {
        int r     = wid * 32 + rl + 8 * j;
        dsto[j]   = (uint32_t)(r * ROWB + q * 16);
        int h     = h0 + r;
        rvalid[j] = (h < H_);
        gbase[j]  = (rvalid[j] ? h : 0) * KK * step;
    }

    int pidx[4];
    auto loadidx = [&](int k) {
#pragma unroll
        for (int j = 0; j < 4; j++)
            pidx[j] = rvalid[j] ? neigh32[gbase[j] + k * step] : -1;
    };
    auto issue = [&](int k) {
        uint32_t dstb = sbase + (k % NSTAGE) * STAGEB;
#pragma unroll
        for (int j = 0; j < 4; j++) {
            unsigned ok = ((unsigned)pidx[j] < (unsigned)H_) ? 16u : 0u;
            const uint4* src = g_xbf + ((size_t)(ok ? pidx[j] : 0) * 4 + q);
            asm volatile("cp.async.cg.shared.global [%0], [%1], 16, %2;"
                         :: "r"(dstb + dsto[j]), "l"(src), "r"(ok) : "memory");
        }
        asm volatile("cp.async.commit_group;" ::: "memory");
    };

    const int rowl = (lane & 7) + ((lane >> 3) & 1) * 8;
    const int byof = (lane >> 4) * 16;

    float d[2][4][4];
#pragma unroll
    for (int a = 0; a < 2; a++)
#pragma unroll
        for (int b = 0; b < 4; b++)
#pragma unroll
            for (int c = 0; c < 4; c++) d[a][b][c] = 0.f;

    loadidx(0); issue(0);
    loadidx(1); issue(1);
    loadidx(2);

#pragma unroll 1
    for (int k = 0; k < KK; k++) {
        if (k + 2 < KK) {
            issue(k + 2);
            if (k + 3 < KK) loadidx(k + 3);
        } else {
            asm volatile("cp.async.commit_group;" ::: "memory");
        }
        asm volatile("cp.async.wait_group 2;" ::: "memory");
        __syncwarp();

        const uint32_t bufb = sbase + (k % NSTAGE) * STAGEB;
        uint32_t aH[2][4], aL[2][4];
#pragma unroll
        for (int mt = 0; mt < 2; mt++) {
            uint32_t ah = bufb + (wid * 32 + mt * 16 + rowl) * ROWB + byof;
            uint32_t al = ah + 32;
            asm volatile("ldmatrix.sync.aligned.m8n8.x4.shared.b16 {%0,%1,%2,%3}, [%4];"
                         : "=r"(aH[mt][0]), "=r"(aH[mt][1]), "=r"(aH[mt][2]), "=r"(aH[mt][3])
                         : "r"(ah));
            asm volatile("ldmatrix.sync.aligned.m8n8.x4.shared.b16 {%0,%1,%2,%3}, [%4];"
                         : "=r"(aL[mt][0]), "=r"(aL[mt][1]), "=r"(aL[mt][2]), "=r"(aL[mt][3])
                         : "r"(al));
        }
#pragma unroll
        for (int nt = 0; nt < 4; nt++) {
            uint2 bh = __ldg(&g_bfrag[((k * 2 + 0) * 4 + nt) * 32 + lane]);
            uint2 bl = __ldg(&g_bfrag[((k * 2 + 1) * 4 + nt) * 32 + lane]);
#pragma unroll
            for (int mt = 0; mt < 2; mt++) {
                MMA_BF16(d[mt][nt], aH[mt], bh);
                MMA_BF16(d[mt][nt], aH[mt], bl);
                MMA_BF16(d[mt][nt], aL[mt], bh);
            }
        }
        __syncwarp();
    }
    asm volatile("cp.async.wait_group 0;" ::: "memory");

    // BN partials from register fragments (deterministic, warp-private).
    const int pidx2 = blockIdx.x * 4 + wid;
#pragma unroll
    for (int nt = 0; nt < 4; nt++) {
        float s0 = 0.f, s1 = 0.f, q0 = 0.f, q1 = 0.f;
#pragma unroll
        for (int mt = 0; mt < 2; mt++) {
            float c0 = d[mt][nt][0], c1 = d[mt][nt][1];
            float c2 = d[mt][nt][2], c3 = d[mt][nt][3];
            s0 += c0 + c2; s1 += c1 + c3;
            q0 += c0 * c0 + c2 * c2; q1 += c1 * c1 + c3 * c3;
        }
#pragma unroll
        for (int off = 4; off < 32; off <<= 1) {
            s0 += __shfl_xor_sync(0xffffffffu, s0, off);
            s1 += __shfl_xor_sync(0xffffffffu, s1, off);
            q0 += __shfl_xor_sync(0xffffffffu, q0, off);
            q1 += __shfl_xor_sync(0xffffffffu, q1, off);
        }
        if ((lane >> 2) == 0) {
            int o0 = nt * 8 + 2 * lane;
            g_partials[o0 * NPART + pidx2]            = s0;
            g_partials[(o0 + 1) * NPART + pidx2]      = s1;
            g_partials[(32 + o0) * NPART + pidx2]     = q0;
            g_partials[(32 + o0 + 1) * NPART + pidx2] = q1;
        }
    }

    // All warps' mainloops/cp.async must drain before Ab is repurposed.
    __syncthreads();

    // Coalesced epilogue: stage D in warp-private smem region, then float4 STG.
    {
        float* stg = reinterpret_cast<float*>(Ab) + wid * (COUT * OPITCH);
#pragma unroll
        for (int nt = 0; nt < 4; nt++) {
            int o0 = nt * 8 + 2 * (lane & 3);
#pragma unroll
            for (int mt = 0; mt < 2; mt++) {
                int hp = mt * 16 + (lane >> 2);     // 0..31 within warp
                stg[o0 * OPITCH + hp]           = d[mt][nt][0];
                stg[(o0 + 1) * OPITCH + hp]     = d[mt][nt][1];
                stg[o0 * OPITCH + hp + 8]       = d[mt][nt][2];
                stg[(o0 + 1) * OPITCH + hp + 8] = d[mt][nt][3];
            }
        }
        __syncwarp();
        const int hq = lane & 7;                    // float4 index along h
        const int h  = h0 + wid * 32 + 4 * hq;      // mult of 4; H_%4==0
        if (h < H_) {
#pragma unroll
            for (int g = 0; g < 8; g++) {
                int o = (lane >> 3) + 4 * g;
                const float* p = stg + o * OPITCH + 4 * hq;
                float4 v = make_float4(p[0], p[1], p[2], p[3]);
                *reinterpret_cast<float4*>(out + (size_t)o * H_ + h) = v;
            }
        }
    }
}

// ---------------------------------------------------------------------------
// Kernel 3: stats stage 1 — 64 rows x SCHUNK chunks; deterministic fp64 tree.
// ---------------------------------------------------------------------------
__global__ void stats1_kernel() {
    const int row   = blockIdx.x;
    const int chunk = blockIdx.y;
    const int per   = (NPART + SCHUNK - 1) / SCHUNK;
    const int b0    = chunk * per;
    const int b1    = (b0 + per < NPART) ? b0 + per : NPART;
    double s = 0.0;
    for (int b = b0 + threadIdx.x; b < b1; b += blockDim.x)
        s += (double)g_partials[row * NPART + b];
    __shared__ double r[256];
    r[threadIdx.x] = s;
    __syncthreads();
    for (int sft = 128; sft > 0; sft >>= 1) {
        if (threadIdx.x < sft) r[threadIdx.x] += r[threadIdx.x + sft];
        __syncthreads();
    }
    if (threadIdx.x == 0) g_red[row * SCHUNK + chunk] = r[0];
}

// ---------------------------------------------------------------------------
// Kernel 4: stats stage 2 — TINY launch (32x32): fold chunk-sums, fp64 math
// done exactly once per channel -> g_scale/g_bias. (The R16 regression was
// doing this in every bn thread: 2.4M x fp64-divide.)
// ---------------------------------------------------------------------------
__global__ void stats2_kernel(const float* __restrict__ gamma,
                              const float* __restrict__ beta) {
    const int o = blockIdx.x;
    if (threadIdx.x == 0) {
        double s1 = 0.0, s2 = 0.0;
#pragma unroll
        for (int c = 0; c < SCHUNK; c++) {
            s1 += g_red[o * SCHUNK + c];
            s2 += g_red[(32 + o) * SCHUNK + c];
        }
        double mean = s1 / (double)H_;
        double var  = s2 / (double)H_ - mean * mean;
        float rstd  = rsqrtf((float)(var + 1e-5));
        float sc    = rstd * gamma[o];
        g_scale[o]  = sc;
        g_bias[o]   = beta[o] - (float)mean * sc;
    }
}

// ---------------------------------------------------------------------------
// Kernel 5: normalize in place (float4; H % 4 == 0) — reads 2 floats/channel.
// ---------------------------------------------------------------------------
__global__ void bn_kernel(float* __restrict__ out) {
    const int o = blockIdx.y;
    const int t = blockIdx.x * blockDim.x + threadIdx.x;
    const float sc = g_scale[o], bi = g_bias[o];
    float4* p = reinterpret_cast<float4*>(out + (size_t)o * H_);
    if (t < H_ / 4) {
        float4 v = p[t];
        v.x = v.x * sc + bi;
        v.y = v.y * sc + bi;
        v.z = v.z * sc + bi;
        v.w = v.w * sc + bi;
        p[t] = v;
    }
}

// ---------------------------------------------------------------------------
extern "C" void kernel_launch(void* const* d_in, const int* in_sizes, int n_in,
                              void* d_out, int out_size) {
    const float* x     = (const float*)d_in[0];  // (1,16,300000,1)
    const float* w     = (const float*)d_in[1];  // (32,16,27)
    const float* gamma = (const float*)d_in[2];  // (32,)
    const float* beta  = (const float*)d_in[3];  // (32,)
    const void*  neigh = d_in[4];                // (300000,27) i64 or i32
    float*       out   = (float*)d_out;          // (1,32,300000,1)

    cudaFuncSetAttribute(conv_kernel,
                         cudaFuncAttributePreferredSharedMemoryCarveout,
                         cudaSharedmemCarveoutMaxShared);

    prep_kernel<<<PREPB + 15, 256>>>(x, w, (const unsigned int*)neigh);
    conv_kernel<<<NBLK, TB>>>((const int*)neigh, out);
    stats1_kernel<<<dim3(64, SCHUNK), 256>>>();
    stats2_kernel<<<COUT, 32>>>(gamma, beta);
    bn_kernel<<<dim3((H_ / 4 + 255) / 256, COUT), 256>>>(out);
}